// round 15
// baseline (speedup 1.0000x reference)
#include <cuda_runtime.h>
#include <cuda_fp16.h>
#include <math.h>

// Problem constants (fixed by setup_inputs)
#define Bq    2
#define Cq    64
#define NBq   9
#define Hq    256
#define Wq    320
#define HWq   (Hq * Wq)              // 81920
#define NCELL (Bq * Hq * Wq)         // 163840
#define NPOS  (Bq * NBq * Hq * Wq)   // 1474560
#define EPSq  1e-5

// ---------------- scratch ------------------------------------------------------
__device__ __align__(16) __half g_ref_t[(size_t)NCELL * Cq];  // [B,H,W,C] fp16 (~21MB)
__device__ __align__(16) float  g_v[(size_t)NPOS * 8];        // correlation vecs (~47MB)
__device__ double g_mom[72];          // [0..63] sum v_i*v_j, [64..71] sum v_i
__device__ double g_st1[16];          // sum / sumsq of y1 (8 ch)
__device__ __align__(16) float g_sc0[16], g_sh0[16];          // folded BN0 (block0 of stats1)

// ---------------- K1: transpose [B,C,H,W] fp32 -> [B,H,W,C] fp16 ----------------
// Block (0,*,0) additionally zeroes the stat accumulators (graph-replay safe:
// every replay re-zeroes before k_gather accumulates).
__global__ void k_transpose(const float* __restrict__ in) {
    __shared__ float tile[64][33];
    int bh = blockIdx.z;                 // b*H + h
    int w0 = blockIdx.x << 5;
    int b  = bh >> 8;                    // H = 256
    int h  = bh & 255;

    if (blockIdx.x == 0 && blockIdx.z == 0) {
        int tid = threadIdx.y * 32 + threadIdx.x;
        if (tid < 72)                    g_mom[tid]      = 0.0;
        else if (tid < 88)               g_st1[tid - 72] = 0.0;
    }

    const float* src = in + (size_t)b * Cq * HWq + (size_t)h * Wq + w0;
    int tx = threadIdx.x, ty = threadIdx.y;
#pragma unroll
    for (int r = 0; r < 4; r++)
        tile[ty + r * 16][tx] = src[(size_t)(ty + r * 16) * HWq + tx];
    __syncthreads();
    __half2* dst = (__half2*)(g_ref_t + (size_t)bh * Wq * Cq) + (size_t)w0 * 32;
#pragma unroll
    for (int r = 0; r < 2; r++) {
        int wl = ty + r * 16;
        dst[(size_t)wl * 32 + tx] =
            __floats2half2_rn(tile[2 * tx][wl], tile[2 * tx + 1][wl]);
    }
}

// ---------------- K2: bilinear gather + correlation + BN0 moments ---------------
// 8 threads per (b,h,w) cell; thread j owns channels j*8..j*8+7 (16B = uint4 in
// fp16). Loops over the 9 neighbors so the center vector is read once. Also
// accumulates sum(v_i) and sum(v_i*v_j) for the BN0 closed-form stats.
#define BLEND2(comp, ck)                                                         \
    {                                                                            \
        float2 fa = __half22float2(*(const __half2*)&Au.comp);                   \
        float2 fb = __half22float2(*(const __half2*)&Bu.comp);                   \
        float2 fc = __half22float2(*(const __half2*)&Cu.comp);                   \
        float2 fd = __half22float2(*(const __half2*)&Du.comp);                   \
        float s0 = fmaf(w11, fd.x, fmaf(w10, fc.x, fmaf(w01, fb.x, w00 * fa.x)));\
        float s1 = fmaf(w11, fd.y, fmaf(w10, fc.y, fmaf(w01, fb.y, w00 * fa.y)));\
        acc = fmaf(s0, cf[ck], acc);                                             \
        acc = fmaf(s1, cf[ck + 1], acc);                                         \
    }

__global__ void __launch_bounds__(256, 4) k_gather(const float* __restrict__ grd) {
    __shared__ float sred[72];
    int t    = blockIdx.x * 256 + threadIdx.x;
    int cell = t >> 3;
    int j    = t & 7;
    int w  = cell % Wq;
    int hh = cell / Wq;
    int h  = hh & (Hq - 1);
    int b  = hh >> 8;

    const uint4* refu = (const uint4*)g_ref_t;    // 8 halves per uint4
    uint4 cu = refu[(size_t)cell * 8 + j];
    float cf[8];
    {
        float2 f;
        f = __half22float2(*(const __half2*)&cu.x); cf[0] = f.x; cf[1] = f.y;
        f = __half22float2(*(const __half2*)&cu.y); cf[2] = f.x; cf[3] = f.y;
        f = __half22float2(*(const __half2*)&cu.z); cf[4] = f.x; cf[5] = f.y;
        f = __half22float2(*(const __half2*)&cu.w); cf[6] = f.x; cf[7] = f.y;
    }

    const uint4* base = refu + (size_t)b * HWq * 8;
    int posb = (b * NBq * Hq + h) * Wq + w;

    float M[8];
#pragma unroll
    for (int i = 0; i < 8; i++) M[i] = 0.0f;
    float Sv = 0.0f;

#pragma unroll 1
    for (int n = 0; n < NBq; n++) {
        int pos = posb + n * HWq;
        float2 g = ((const float2*)grd)[pos];
        float ix = fminf(fmaxf(((g.x + 1.0f) * (float)Wq - 1.0f) * 0.5f, 0.0f), (float)(Wq - 1));
        float iy = fminf(fmaxf(((g.y + 1.0f) * (float)Hq - 1.0f) * 0.5f, 0.0f), (float)(Hq - 1));
        float fx = floorf(ix), fy = floorf(iy);
        float ax = ix - fx,    ay = iy - fy;
        int x0 = (int)fx,      y0 = (int)fy;
        int x1 = min(x0 + 1, Wq - 1), y1 = min(y0 + 1, Hq - 1);
        float w00 = (1.0f - ax) * (1.0f - ay);
        float w01 = ax * (1.0f - ay);
        float w10 = (1.0f - ax) * ay;
        float w11 = ax * ay;

        uint4 Au = base[(size_t)(y0 * Wq + x0) * 8 + j];
        uint4 Bu = base[(size_t)(y0 * Wq + x1) * 8 + j];
        uint4 Cu = base[(size_t)(y1 * Wq + x0) * 8 + j];
        uint4 Du = base[(size_t)(y1 * Wq + x1) * 8 + j];

        float acc = 0.0f;
        BLEND2(x, 0) BLEND2(y, 2) BLEND2(z, 4) BLEND2(w, 6)

        float v = acc * 0.125f;            // mean over C/G = 8 (exact)
        g_v[(size_t)pos * 8 + j] = v;

        Sv += v;
#pragma unroll
        for (int i = 0; i < 8; i++) {
            float vi = __shfl_sync(0xffffffffu, v, i, 8);
            M[i] = fmaf(vi, v, M[i]);
        }
    }

    // reduce across the 4 groups in the warp (lanes j, j+8, j+16, j+24)
#pragma unroll
    for (int i = 0; i < 8; i++) {
        M[i] += __shfl_down_sync(0xffffffffu, M[i], 16);
        M[i] += __shfl_down_sync(0xffffffffu, M[i], 8);
    }
    Sv += __shfl_down_sync(0xffffffffu, Sv, 16);
    Sv += __shfl_down_sync(0xffffffffu, Sv, 8);

    if (threadIdx.x < 72) sred[threadIdx.x] = 0.0f;
    __syncthreads();
    if ((threadIdx.x & 31) < 8) {
#pragma unroll
        for (int i = 0; i < 8; i++) atomicAdd(&sred[i * 8 + j], M[i]);
        atomicAdd(&sred[64 + j], Sv);
    }
    __syncthreads();
    if (threadIdx.x < 72) atomicAdd(&g_mom[threadIdx.x], (double)sred[threadIdx.x]);
}

// helper: warp-reduce then one shared atomic per warp
__device__ __forceinline__ void block_acc(float val, float* slot) {
#pragma unroll
    for (int off = 16; off; off >>= 1)
        val += __shfl_down_sync(0xffffffffu, val, off);
    if ((threadIdx.x & 31) == 0) atomicAdd(slot, val);
}

// ---------------- K3: BN0 fold (per-block prologue) + BN1 stats ------------------
__global__ void __launch_bounds__(256, 4) k_stats1(const float* __restrict__ w0,
                                                   const float* __restrict__ w1,
                                                   const float* __restrict__ g0,
                                                   const float* __restrict__ b0) {
    __shared__ float sw0[128], sw1[128], ssc[16], ssh[16];
    __shared__ float red[16];
    int tid = threadIdx.x;
    if (tid < 128) { sw0[tid] = w0[tid]; sw1[tid] = w1[tid]; }
    if (tid < 16)  red[tid] = 0.0f;

    // BN0 fold from moments, recomputed per block (deterministic, L2-hot input)
    if (tid < 16) {
        const double N = (double)NPOS;
        double wr[8];
#pragma unroll
        for (int i = 0; i < 8; i++) wr[i] = (double)w0[tid * 8 + i];
        double m = 0.0, e2 = 0.0;
#pragma unroll
        for (int i = 0; i < 8; i++) {
            m = fma(wr[i], g_mom[64 + i], m);
            double r0 = 0.0, r1 = 0.0;
#pragma unroll
            for (int k = 0; k < 8; k += 2) {
                r0 = fma(wr[k],     g_mom[i * 8 + k],     r0);
                r1 = fma(wr[k + 1], g_mom[i * 8 + k + 1], r1);
            }
            e2 = fma(wr[i], r0 + r1, e2);
        }
        m /= N; e2 /= N;
        double rstd = rsqrt(e2 - m * m + EPSq);
        double gg   = (double)g0[tid];
        float sc = (float)(gg * rstd);
        float sh = (float)((double)b0[tid] - m * rstd * gg);
        ssc[tid] = sc; ssh[tid] = sh;
        if (blockIdx.x == 0) { g_sc0[tid] = sc; g_sh0[tid] = sh; }  // for k_final
    }
    __syncthreads();

    float s[8], q[8];
#pragma unroll
    for (int o = 0; o < 8; o++) { s[o] = 0.0f; q[o] = 0.0f; }

    for (int pos = blockIdx.x * 256 + tid; pos < NPOS; pos += gridDim.x * 256) {
        const float4* pv = (const float4*)(g_v + (size_t)pos * 8);
        float4 v0 = pv[0], v1 = pv[1];
        float v[8] = {v0.x, v0.y, v0.z, v0.w, v1.x, v1.y, v1.z, v1.w};
        float z[16];
#pragma unroll
        for (int o = 0; o < 16; o++) {
            float y = 0.0f;
#pragma unroll
            for (int i = 0; i < 8; i++) y = fmaf(sw0[o * 8 + i], v[i], y);
            z[o] = fmaxf(fmaf(y, ssc[o], ssh[o]), 0.0f);
        }
#pragma unroll
        for (int o = 0; o < 8; o++) {
            float y = 0.0f;
#pragma unroll
            for (int i = 0; i < 16; i++) y = fmaf(sw1[o * 16 + i], z[i], y);
            s[o] += y;
            q[o]  = fmaf(y, y, q[o]);
        }
    }
#pragma unroll
    for (int o = 0; o < 8; o++) { block_acc(s[o], &red[o]); block_acc(q[o], &red[8 + o]); }
    __syncthreads();
    if (tid < 16) atomicAdd(&g_st1[tid], (double)red[tid]);
}

// ---------------- K4: BN1 fold (per-block prologue) + final MLP + sigmoid --------
__global__ void __launch_bounds__(256, 4) k_final(const float* __restrict__ w0,
                                                  const float* __restrict__ w1,
                                                  const float* __restrict__ ws,
                                                  const float* __restrict__ bs,
                                                  const float* __restrict__ g1,
                                                  const float* __restrict__ b1,
                                                  float* __restrict__ out) {
    __shared__ float sw0[128], sw1[128], ssc0[16], ssh0[16], ssc1[8], ssh1[8], sws[8];
    __shared__ float sbs;
    int tid = threadIdx.x;
    if (tid < 128) { sw0[tid] = w0[tid]; sw1[tid] = w1[tid]; }
    if (tid < 16)  { ssc0[tid] = g_sc0[tid]; ssh0[tid] = g_sh0[tid]; }
    if (tid < 8) {
        // BN1 fold from g_st1, recomputed per block (cheap, deterministic)
        const double N = (double)NPOS;
        double m    = g_st1[tid] / N;
        double var  = g_st1[8 + tid] / N - m * m;
        double rstd = rsqrt(var + EPSq);
        double gg   = (double)g1[tid];
        ssc1[tid] = (float)(gg * rstd);
        ssh1[tid] = (float)((double)b1[tid] - m * rstd * gg);
        sws[tid]  = ws[tid];
    }
    if (tid == 0) sbs = bs[0];
    __syncthreads();

    int pos = blockIdx.x * 256 + tid;   // grid sized exactly

    const float4* pv = (const float4*)(g_v + (size_t)pos * 8);
    float4 v0 = pv[0], v1 = pv[1];
    float v[8] = {v0.x, v0.y, v0.z, v0.w, v1.x, v1.y, v1.z, v1.w};

    float z[16];
#pragma unroll
    for (int o = 0; o < 16; o++) {
        float y = 0.0f;
#pragma unroll
        for (int i = 0; i < 8; i++) y = fmaf(sw0[o * 8 + i], v[i], y);
        z[o] = fmaxf(fmaf(y, ssc0[o], ssh0[o]), 0.0f);
    }
    float acc = sbs;
#pragma unroll
    for (int o = 0; o < 8; o++) {
        float y = 0.0f;
#pragma unroll
        for (int i = 0; i < 16; i++) y = fmaf(sw1[o * 16 + i], z[i], y);
        float z1 = fmaxf(fmaf(y, ssc1[o], ssh1[o]), 0.0f);
        acc = fmaf(sws[o], z1, acc);
    }

    out[pos] = __fdividef(1.0f, 1.0f + __expf(-acc));
}

// ---------------- launch --------------------------------------------------------
extern "C" void kernel_launch(void* const* d_in, const int* in_sizes, int n_in,
                              void* d_out, int out_size) {
    const float* ref  = (const float*)d_in[0];
    const float* grid = (const float*)d_in[1];
    const float* w0   = (const float*)d_in[2];
    const float* g0   = (const float*)d_in[3];
    const float* b0   = (const float*)d_in[4];
    const float* w1   = (const float*)d_in[5];
    const float* g1   = (const float*)d_in[6];
    const float* b1   = (const float*)d_in[7];
    const float* ws   = (const float*)d_in[8];
    const float* bs   = (const float*)d_in[9];
    float* out = (float*)d_out;

    k_transpose<<<dim3(Wq / 32, 1, Bq * Hq), dim3(32, 16)>>>(ref);
    k_gather<<<(NCELL * 8) / 256, 256>>>(grid);                  // 5120 blocks, exact
    k_stats1<<<1440, 256>>>(w0, w1, g0, b0);                     // 4 grid-stride iters
    k_final<<<NPOS / 256, 256>>>(w0, w1, ws, bs, g1, b1, out);   // 5760 blocks, exact
}

// round 16
// speedup vs baseline: 1.0106x; 1.0106x over previous
#include <cuda_runtime.h>
#include <cuda_fp16.h>
#include <math.h>

// Problem constants (fixed by setup_inputs)
#define Bq    2
#define Cq    64
#define NBq   9
#define Hq    256
#define Wq    320
#define HWq   (Hq * Wq)              // 81920
#define NCELL (Bq * Hq * Wq)         // 163840
#define NPOS  (Bq * NBq * Hq * Wq)   // 1474560
#define EPSq  1e-5

// ---------------- scratch ------------------------------------------------------
__device__ __align__(16) __half g_ref_t[(size_t)NCELL * Cq];  // [B,H,W,C] fp16 (~21MB)
__device__ __align__(16) float  g_v[(size_t)NPOS * 8];        // correlation vecs (~47MB)
__device__ double g_mom[72];          // [0..63] sum v_i*v_j, [64..71] sum v_i
__device__ double g_st1[16];          // sum / sumsq of y1 (8 ch)
__device__ __align__(16) float g_sc0[16], g_sh0[16];          // folded BN0 (block0 of stats1)

// ---------------- K1: transpose [B,C,H,W] fp32 -> [B,H,W,C] fp16 ----------------
// Block (0,*,0) additionally zeroes the stat accumulators (graph-replay safe:
// every replay re-zeroes before k_gather accumulates).
__global__ void k_transpose(const float* __restrict__ in) {
    __shared__ float tile[64][33];
    int bh = blockIdx.z;                 // b*H + h
    int w0 = blockIdx.x << 5;
    int b  = bh >> 8;                    // H = 256
    int h  = bh & 255;

    if (blockIdx.x == 0 && blockIdx.z == 0) {
        int tid = threadIdx.y * 32 + threadIdx.x;
        if (tid < 72)                    g_mom[tid]      = 0.0;
        else if (tid < 88)               g_st1[tid - 72] = 0.0;
    }

    const float* src = in + (size_t)b * Cq * HWq + (size_t)h * Wq + w0;
    int tx = threadIdx.x, ty = threadIdx.y;
#pragma unroll
    for (int r = 0; r < 4; r++)
        tile[ty + r * 16][tx] = src[(size_t)(ty + r * 16) * HWq + tx];
    __syncthreads();
    __half2* dst = (__half2*)(g_ref_t + (size_t)bh * Wq * Cq) + (size_t)w0 * 32;
#pragma unroll
    for (int r = 0; r < 2; r++) {
        int wl = ty + r * 16;
        dst[(size_t)wl * 32 + tx] =
            __floats2half2_rn(tile[2 * tx][wl], tile[2 * tx + 1][wl]);
    }
}

// ---------------- K2: bilinear gather + correlation + BN0 moments ---------------
// 8 threads per (b,h,w) cell; thread j owns channels j*8..j*8+7 (16B = uint4 in
// fp16). Loops over the 9 neighbors so the center vector is read once. Also
// accumulates sum(v_i) and sum(v_i*v_j) for the BN0 closed-form stats.
#define BLEND2(comp, ck)                                                         \
    {                                                                            \
        float2 fa = __half22float2(*(const __half2*)&Au.comp);                   \
        float2 fb = __half22float2(*(const __half2*)&Bu.comp);                   \
        float2 fc = __half22float2(*(const __half2*)&Cu.comp);                   \
        float2 fd = __half22float2(*(const __half2*)&Du.comp);                   \
        float s0 = fmaf(w11, fd.x, fmaf(w10, fc.x, fmaf(w01, fb.x, w00 * fa.x)));\
        float s1 = fmaf(w11, fd.y, fmaf(w10, fc.y, fmaf(w01, fb.y, w00 * fa.y)));\
        acc = fmaf(s0, cf[ck], acc);                                             \
        acc = fmaf(s1, cf[ck + 1], acc);                                         \
    }

__global__ void __launch_bounds__(256, 4) k_gather(const float* __restrict__ grd) {
    __shared__ float sred[72];
    int t    = blockIdx.x * 256 + threadIdx.x;
    int cell = t >> 3;
    int j    = t & 7;
    int w  = cell % Wq;
    int hh = cell / Wq;
    int h  = hh & (Hq - 1);
    int b  = hh >> 8;

    const uint4* refu = (const uint4*)g_ref_t;    // 8 halves per uint4
    uint4 cu = refu[(size_t)cell * 8 + j];
    float cf[8];
    {
        float2 f;
        f = __half22float2(*(const __half2*)&cu.x); cf[0] = f.x; cf[1] = f.y;
        f = __half22float2(*(const __half2*)&cu.y); cf[2] = f.x; cf[3] = f.y;
        f = __half22float2(*(const __half2*)&cu.z); cf[4] = f.x; cf[5] = f.y;
        f = __half22float2(*(const __half2*)&cu.w); cf[6] = f.x; cf[7] = f.y;
    }

    const uint4* base = refu + (size_t)b * HWq * 8;
    int posb = (b * NBq * Hq + h) * Wq + w;

    float M[8];
#pragma unroll
    for (int i = 0; i < 8; i++) M[i] = 0.0f;
    float Sv = 0.0f;

#pragma unroll 1
    for (int n = 0; n < NBq; n++) {
        int pos = posb + n * HWq;
        float2 g = ((const float2*)grd)[pos];
        float ix = fminf(fmaxf(((g.x + 1.0f) * (float)Wq - 1.0f) * 0.5f, 0.0f), (float)(Wq - 1));
        float iy = fminf(fmaxf(((g.y + 1.0f) * (float)Hq - 1.0f) * 0.5f, 0.0f), (float)(Hq - 1));
        float fx = floorf(ix), fy = floorf(iy);
        float ax = ix - fx,    ay = iy - fy;
        int x0 = (int)fx,      y0 = (int)fy;
        int x1 = min(x0 + 1, Wq - 1), y1 = min(y0 + 1, Hq - 1);
        float w00 = (1.0f - ax) * (1.0f - ay);
        float w01 = ax * (1.0f - ay);
        float w10 = (1.0f - ax) * ay;
        float w11 = ax * ay;

        uint4 Au = base[(size_t)(y0 * Wq + x0) * 8 + j];
        uint4 Bu = base[(size_t)(y0 * Wq + x1) * 8 + j];
        uint4 Cu = base[(size_t)(y1 * Wq + x0) * 8 + j];
        uint4 Du = base[(size_t)(y1 * Wq + x1) * 8 + j];

        float acc = 0.0f;
        BLEND2(x, 0) BLEND2(y, 2) BLEND2(z, 4) BLEND2(w, 6)

        float v = acc * 0.125f;            // mean over C/G = 8 (exact)
        g_v[(size_t)pos * 8 + j] = v;

        Sv += v;
#pragma unroll
        for (int i = 0; i < 8; i++) {
            float vi = __shfl_sync(0xffffffffu, v, i, 8);
            M[i] = fmaf(vi, v, M[i]);
        }
    }

    // reduce across the 4 groups in the warp (lanes j, j+8, j+16, j+24)
#pragma unroll
    for (int i = 0; i < 8; i++) {
        M[i] += __shfl_down_sync(0xffffffffu, M[i], 16);
        M[i] += __shfl_down_sync(0xffffffffu, M[i], 8);
    }
    Sv += __shfl_down_sync(0xffffffffu, Sv, 16);
    Sv += __shfl_down_sync(0xffffffffu, Sv, 8);

    if (threadIdx.x < 72) sred[threadIdx.x] = 0.0f;
    __syncthreads();
    if ((threadIdx.x & 31) < 8) {
#pragma unroll
        for (int i = 0; i < 8; i++) atomicAdd(&sred[i * 8 + j], M[i]);
        atomicAdd(&sred[64 + j], Sv);
    }
    __syncthreads();
    if (threadIdx.x < 72) atomicAdd(&g_mom[threadIdx.x], (double)sred[threadIdx.x]);
}

// helper: warp-reduce then one shared atomic per warp
__device__ __forceinline__ void block_acc(float val, float* slot) {
#pragma unroll
    for (int off = 16; off; off >>= 1)
        val += __shfl_down_sync(0xffffffffu, val, off);
    if ((threadIdx.x & 31) == 0) atomicAdd(slot, val);
}

// ---------------- K3: BN0 fold (per-block prologue) + BN1 stats ------------------
__global__ void __launch_bounds__(256, 4) k_stats1(const float* __restrict__ w0,
                                                   const float* __restrict__ w1,
                                                   const float* __restrict__ g0,
                                                   const float* __restrict__ b0) {
    __shared__ float sw0[128], sw1[128], ssc[16], ssh[16];
    __shared__ float red[16];
    int tid = threadIdx.x;
    if (tid < 128) { sw0[tid] = w0[tid]; sw1[tid] = w1[tid]; }
    if (tid < 16)  red[tid] = 0.0f;

    // BN0 fold from moments, recomputed per block (deterministic, L2-hot input)
    if (tid < 16) {
        const double N = (double)NPOS;
        double wr[8];
#pragma unroll
        for (int i = 0; i < 8; i++) wr[i] = (double)w0[tid * 8 + i];
        double m = 0.0, e2 = 0.0;
#pragma unroll
        for (int i = 0; i < 8; i++) {
            m = fma(wr[i], g_mom[64 + i], m);
            double r0 = 0.0, r1 = 0.0;
#pragma unroll
            for (int k = 0; k < 8; k += 2) {
                r0 = fma(wr[k],     g_mom[i * 8 + k],     r0);
                r1 = fma(wr[k + 1], g_mom[i * 8 + k + 1], r1);
            }
            e2 = fma(wr[i], r0 + r1, e2);
        }
        m /= N; e2 /= N;
        double rstd = rsqrt(e2 - m * m + EPSq);
        double gg   = (double)g0[tid];
        float sc = (float)(gg * rstd);
        float sh = (float)((double)b0[tid] - m * rstd * gg);
        ssc[tid] = sc; ssh[tid] = sh;
        if (blockIdx.x == 0) { g_sc0[tid] = sc; g_sh0[tid] = sh; }  // for k_final
    }
    __syncthreads();

    float s[8], q[8];
#pragma unroll
    for (int o = 0; o < 8; o++) { s[o] = 0.0f; q[o] = 0.0f; }

    for (int pos = blockIdx.x * 256 + tid; pos < NPOS; pos += gridDim.x * 256) {
        const float4* pv = (const float4*)(g_v + (size_t)pos * 8);
        float4 v0 = pv[0], v1 = pv[1];
        float v[8] = {v0.x, v0.y, v0.z, v0.w, v1.x, v1.y, v1.z, v1.w};
        float z[16];
#pragma unroll
        for (int o = 0; o < 16; o++) {
            float y = 0.0f;
#pragma unroll
            for (int i = 0; i < 8; i++) y = fmaf(sw0[o * 8 + i], v[i], y);
            z[o] = fmaxf(fmaf(y, ssc[o], ssh[o]), 0.0f);
        }
#pragma unroll
        for (int o = 0; o < 8; o++) {
            float y = 0.0f;
#pragma unroll
            for (int i = 0; i < 16; i++) y = fmaf(sw1[o * 16 + i], z[i], y);
            s[o] += y;
            q[o]  = fmaf(y, y, q[o]);
        }
    }
#pragma unroll
    for (int o = 0; o < 8; o++) { block_acc(s[o], &red[o]); block_acc(q[o], &red[8 + o]); }
    __syncthreads();
    if (tid < 16) atomicAdd(&g_st1[tid], (double)red[tid]);
}

// ---------------- K4: BN1 fold (per-block prologue) + final MLP + sigmoid --------
__global__ void __launch_bounds__(256, 4) k_final(const float* __restrict__ w0,
                                                  const float* __restrict__ w1,
                                                  const float* __restrict__ ws,
                                                  const float* __restrict__ bs,
                                                  const float* __restrict__ g1,
                                                  const float* __restrict__ b1,
                                                  float* __restrict__ out) {
    __shared__ float sw0[128], sw1[128], ssc0[16], ssh0[16], ssc1[8], ssh1[8], sws[8];
    __shared__ float sbs;
    int tid = threadIdx.x;
    if (tid < 128) { sw0[tid] = w0[tid]; sw1[tid] = w1[tid]; }
    if (tid < 16)  { ssc0[tid] = g_sc0[tid]; ssh0[tid] = g_sh0[tid]; }
    if (tid < 8) {
        // BN1 fold from g_st1, recomputed per block (cheap, deterministic)
        const double N = (double)NPOS;
        double m    = g_st1[tid] / N;
        double var  = g_st1[8 + tid] / N - m * m;
        double rstd = rsqrt(var + EPSq);
        double gg   = (double)g1[tid];
        ssc1[tid] = (float)(gg * rstd);
        ssh1[tid] = (float)((double)b1[tid] - m * rstd * gg);
        sws[tid]  = ws[tid];
    }
    if (tid == 0) sbs = bs[0];
    __syncthreads();

    int pos = blockIdx.x * 256 + tid;   // grid sized exactly

    const float4* pv = (const float4*)(g_v + (size_t)pos * 8);
    float4 v0 = pv[0], v1 = pv[1];
    float v[8] = {v0.x, v0.y, v0.z, v0.w, v1.x, v1.y, v1.z, v1.w};

    float z[16];
#pragma unroll
    for (int o = 0; o < 16; o++) {
        float y = 0.0f;
#pragma unroll
        for (int i = 0; i < 8; i++) y = fmaf(sw0[o * 8 + i], v[i], y);
        z[o] = fmaxf(fmaf(y, ssc0[o], ssh0[o]), 0.0f);
    }
    float acc = sbs;
#pragma unroll
    for (int o = 0; o < 8; o++) {
        float y = 0.0f;
#pragma unroll
        for (int i = 0; i < 16; i++) y = fmaf(sw1[o * 16 + i], z[i], y);
        float z1 = fmaxf(fmaf(y, ssc1[o], ssh1[o]), 0.0f);
        acc = fmaf(sws[o], z1, acc);
    }

    out[pos] = __fdividef(1.0f, 1.0f + __expf(-acc));
}

// ---------------- launch --------------------------------------------------------
extern "C" void kernel_launch(void* const* d_in, const int* in_sizes, int n_in,
                              void* d_out, int out_size) {
    const float* ref  = (const float*)d_in[0];
    const float* grid = (const float*)d_in[1];
    const float* w0   = (const float*)d_in[2];
    const float* g0   = (const float*)d_in[3];
    const float* b0   = (const float*)d_in[4];
    const float* w1   = (const float*)d_in[5];
    const float* g1   = (const float*)d_in[6];
    const float* b1   = (const float*)d_in[7];
    const float* ws   = (const float*)d_in[8];
    const float* bs   = (const float*)d_in[9];
    float* out = (float*)d_out;

    k_transpose<<<dim3(Wq / 32, 1, Bq * Hq), dim3(32, 16)>>>(ref);
    k_gather<<<(NCELL * 8) / 256, 256>>>(grid);                  // 5120 blocks, exact
    k_stats1<<<1440, 256>>>(w0, w1, g0, b0);                     // 4 grid-stride iters
    k_final<<<NPOS / 256, 256>>>(w0, w1, ws, bs, g1, b1, out);   // 5760 blocks, exact
}